// round 14
// baseline (speedup 1.0000x reference)
#include <cuda_runtime.h>
#include <cuda_bf16.h>
#include <cstdint>

#define BATCH 16
#define T_MEL 16
#define FEAT 80
#define NCLASS 512
#define RNN 512
#define D_IN 592
#define G3 1536
#define T_OUT 3300
#define M_ROWS (T_OUT * BATCH)

#define NGRP 4          // independent batch groups
#define GRP_CTAS 32     // CTAs per group
#define NB 4            // batches per group
#define UNITS 16        // units per CTA  (32*16 = 512)

typedef unsigned long long ull;

// ---------------- device scratch (no allocation allowed) ----------------
__device__ float g_melT[(size_t)M_ROWS * FEAT];
__device__ float g_xproj[(size_t)M_ROWS * G3];
__device__ float g_hs[(size_t)M_ROWS * RNN];
__device__ float g_f1[(size_t)M_ROWS * RNN];
__device__ float g_hgrp[NGRP][2][NB][RNN];        // per-group ping-pong h
__device__ unsigned g_gflags[NGRP * GRP_CTAS * 8]; // per-CTA flags, 32B apart

// ---------------- helpers ----------------
__device__ __forceinline__ ull pack2(float x, float y) {
    ull r; asm("mov.b64 %0,{%1,%2};" : "=l"(r) : "f"(x), "f"(y)); return r;
}
__device__ __forceinline__ void fma2(ull& d, ull a, ull b) {
    asm("fma.rn.f32x2 %0,%1,%2,%3;" : "=l"(d) : "l"(a), "l"(b), "l"(d));
}
__device__ __forceinline__ float lohi(ull a) {
    float x, y; asm("mov.b64 {%0,%1},%2;" : "=f"(x), "=f"(y) : "l"(a)); return x + y;
}
__device__ __forceinline__ void unpk(ull a, float& x, float& y) {
    asm("mov.b64 {%0,%1},%2;" : "=f"(x), "=f"(y) : "l"(a));
}

// ---------------- init ----------------
__global__ void k_init() {
    int i = blockIdx.x * blockDim.x + threadIdx.x;
    if (i < NGRP * GRP_CTAS * 8) g_gflags[i] = 0u;
    if (i < NGRP * 2 * NB * RNN) ((float*)g_hgrp)[i] = 0.f;
}

// ---------------- fused 3-stage upsample ----------------
__global__ void __launch_bounds__(256)
k_upsample_all(const float* __restrict__ mels,
               const float* __restrict__ k0,
               const float* __restrict__ k1,
               const float* __restrict__ k2) {
    __shared__ float s16[16];
    __shared__ float s80[80];
    __shared__ float s400[400];
    __shared__ float sk0[11], sk1[11], sk2[23];
    const int bf = blockIdx.x, b = bf / FEAT, f = bf % FEAT;
    const int tid = threadIdx.x;

    if (tid < 16) s16[tid] = mels[(size_t)bf * T_MEL + tid];
    if (tid < 11) { sk0[tid] = k0[tid]; sk1[tid] = k1[tid]; }
    if (tid < 23) sk2[tid] = k2[tid];
    __syncthreads();

    if (tid < 80) {
        float a = 0.f;
        #pragma unroll
        for (int j = 0; j < 11; ++j) {
            int u = tid + j - 5;
            if (u >= 0 && u < 80) a += sk0[j] * s16[u / 5];
        }
        s80[tid] = a;
    }
    __syncthreads();

    for (int t = tid; t < 400; t += 256) {
        float a = 0.f;
        #pragma unroll
        for (int j = 0; j < 11; ++j) {
            int u = t + j - 5;
            if (u >= 0 && u < 400) a += sk1[j] * s80[u / 5];
        }
        s400[t] = a;
    }
    __syncthreads();

    for (int t = tid; t < T_OUT; t += 256) {
        const int tp = t + 550;
        float a = 0.f;
        #pragma unroll
        for (int j = 0; j < 23; ++j) {
            int u = tp + j - 11;
            if (u >= 0 && u < 4400) a += sk2[j] * s400[u / 11];
        }
        g_melT[((size_t)t * BATCH + b) * FEAT + f] = a;
    }
}

// ---------------- fp32 GEMM (f32x2 inner): C[M,N] = A[M,K] @ B[N,K]^T -------
// mode 0: xproj (+b_ih + w_ih[g, x[b,t]]), mode 1: fc1 relu, mode 2: fc2 -> out
#define BM 64
#define BN 64
#define BK 16
#define SSTR 68

__global__ void __launch_bounds__(256)
k_gemm(const float* __restrict__ A, int lda,
       const float* __restrict__ Bw, int ldb, int KT,
       const float* __restrict__ bias, float* __restrict__ C,
       int mode, const int* __restrict__ xidx, const float* __restrict__ w_ih_full) {
    __shared__ float As[BK * SSTR];
    __shared__ float Bs[BK * SSTR];
    const int tid = threadIdx.x;
    const int m0 = blockIdx.x * BM, n0 = blockIdx.y * BN;
    const int ty = tid >> 4, tx = tid & 15;
    const int fr = tid >> 2, fc = (tid & 3) * 4;

    ull c2[4][2];   // [m][n-pair]: packs columns (2p, 2p+1)
    #pragma unroll
    for (int i = 0; i < 4; ++i) { c2[i][0] = 0ull; c2[i][1] = 0ull; }

    for (int kt = 0; kt < KT; ++kt) {
        const int k0 = kt * BK;
        float4 va = *reinterpret_cast<const float4*>(&A[(size_t)(m0 + fr) * lda + k0 + fc]);
        float4 vb = *reinterpret_cast<const float4*>(&Bw[(size_t)(n0 + fr) * ldb + k0 + fc]);
        As[(fc + 0) * SSTR + fr] = va.x; As[(fc + 1) * SSTR + fr] = va.y;
        As[(fc + 2) * SSTR + fr] = va.z; As[(fc + 3) * SSTR + fr] = va.w;
        Bs[(fc + 0) * SSTR + fr] = vb.x; Bs[(fc + 1) * SSTR + fr] = vb.y;
        Bs[(fc + 2) * SSTR + fr] = vb.z; Bs[(fc + 3) * SSTR + fr] = vb.w;
        __syncthreads();
        #pragma unroll
        for (int kk = 0; kk < BK; ++kk) {
            const ull* bp = reinterpret_cast<const ull*>(&Bs[kk * SSTR + tx * 4]);
            ull b01 = bp[0], b23 = bp[1];
            float4 a4 = *reinterpret_cast<const float4*>(&As[kk * SSTR + ty * 4]);
            ull a0 = pack2(a4.x, a4.x), a1 = pack2(a4.y, a4.y);
            ull a2 = pack2(a4.z, a4.z), a3 = pack2(a4.w, a4.w);
            fma2(c2[0][0], a0, b01); fma2(c2[0][1], a0, b23);
            fma2(c2[1][0], a1, b01); fma2(c2[1][1], a1, b23);
            fma2(c2[2][0], a2, b01); fma2(c2[2][1], a2, b23);
            fma2(c2[3][0], a3, b01); fma2(c2[3][1], a3, b23);
        }
        __syncthreads();
    }

    #pragma unroll
    for (int im = 0; im < 4; ++im) {
        float cc[4];
        unpk(c2[im][0], cc[0], cc[1]);
        unpk(c2[im][1], cc[2], cc[3]);
        const int r = m0 + ty * 4 + im;
        const int t = r >> 4, b = r & 15;
        int xv = 0;
        if (mode == 0) xv = xidx[b * T_OUT + t];
        #pragma unroll
        for (int in_ = 0; in_ < 4; ++in_) {
            const int g = n0 + tx * 4 + in_;
            float v = cc[in_] + bias[g];
            if (mode == 0) {
                v += w_ih_full[(size_t)g * D_IN + xv];
                C[(size_t)r * G3 + g] = v;
            } else if (mode == 1) {
                C[(size_t)r * RNN + g] = fmaxf(v, 0.f);
            } else {
                C[((size_t)b * T_OUT + t) * NCLASS + g] = v;
            }
        }
    }
}

// ---------------- persistent GRU: batch groups, weights in registers --------
// grid 128 = 4 groups x 32 CTAs. CTA: 16 units, 4 batches, 256 threads.
__global__ void __launch_bounds__(256, 1)
k_gru(const float* __restrict__ w_hh, const float* __restrict__ b_hh) {
    __shared__ float hstage[NB][RNN];          // this group's h (8 KB)
    __shared__ float sred[8][48][NB];          // per-warp partials
    __shared__ float bias_s[48];

    const int cta = blockIdx.x, grp = cta >> 5, c = cta & 31, u0 = c * UNITS;
    const int tid = threadIdx.x;
    const int rg = tid & 7, ks = tid >> 3, warp = tid >> 5, lane = tid & 31;
    const int ul = tid >> 2, bl = tid & 3;     // gate threads (tid<64)
    const int bglob = grp * NB + bl;

    // load weights into registers (static row/k mapping)
    ull w[6][8];
    #pragma unroll
    for (int i = 0; i < 6; ++i) {
        const int m = rg * 6 + i;               // 0..47
        const int gate = m >> 4, uloc = m & 15;
        const float* wp = w_hh + ((size_t)(gate * RNN + u0 + uloc)) * RNN + ks * 16;
        #pragma unroll
        for (int j = 0; j < 8; ++j)
            w[i][j] = *reinterpret_cast<const ull*>(wp + 2 * j);
    }
    if (tid < 48) bias_s[tid] = b_hh[(tid >> 4) * RNN + u0 + (tid & 15)];

    // x_proj preload for t = 0 (gate threads)
    float xpr = 0.f, xpz = 0.f, xpn = 0.f;
    if (tid < 64) {
        size_t ro = (size_t)bglob * G3 + u0 + ul;
        xpr = __ldg(&g_xproj[ro]);
        xpz = __ldg(&g_xproj[ro + 512]);
        xpn = __ldg(&g_xproj[ro + 1024]);
    }
    __syncthreads();

    unsigned* myflag = &g_gflags[(grp * GRP_CTAS + c) * 8];
    unsigned* grpflags = &g_gflags[grp * GRP_CTAS * 8];
    int cur = 0;
    for (int t = 0; t < T_OUT; ++t) {
        // stage this group's h (2048 floats) into smem cooperatively
        {
            const float* hsrc = &g_hgrp[grp][cur][0][0];
            float4 v0 = __ldcg(reinterpret_cast<const float4*>(hsrc + tid * 8));
            float4 v1 = __ldcg(reinterpret_cast<const float4*>(hsrc + tid * 8 + 4));
            *reinterpret_cast<float4*>(&hstage[0][0] + tid * 8) = v0;
            *reinterpret_cast<float4*>(&hstage[0][0] + tid * 8 + 4) = v1;
        }
        // prefetch next step's x_proj
        float nxr = 0.f, nxz = 0.f, nxn = 0.f;
        if (tid < 64 && t + 1 < T_OUT) {
            size_t ro = ((size_t)(t + 1) * 16 + bglob) * G3 + u0 + ul;
            nxr = __ldg(&g_xproj[ro]);
            nxz = __ldg(&g_xproj[ro + 512]);
            nxn = __ldg(&g_xproj[ro + 1024]);
        }
        __syncthreads();   // hstage ready

        // dot products: 6 rows x 16 k x 4 batches, weights in regs
        ull acc[6][NB];
        #pragma unroll
        for (int i = 0; i < 6; ++i)
            #pragma unroll
            for (int b = 0; b < NB; ++b) acc[i][b] = 0ull;

        #pragma unroll
        for (int b = 0; b < NB; ++b) {
            ull h2[8];
            #pragma unroll
            for (int j = 0; j < 4; ++j) {
                float4 v = *reinterpret_cast<const float4*>(&hstage[b][ks * 16 + 4 * j]);
                h2[2 * j]     = pack2(v.x, v.y);
                h2[2 * j + 1] = pack2(v.z, v.w);
            }
            #pragma unroll
            for (int i = 0; i < 6; ++i)
                #pragma unroll
                for (int j = 0; j < 8; ++j)
                    fma2(acc[i][b], w[i][j], h2[j]);
        }

        // reduce over k: lane bits 3,4 carry ks&3
        float part[6][NB];
        #pragma unroll
        for (int i = 0; i < 6; ++i)
            #pragma unroll
            for (int b = 0; b < NB; ++b) {
                float v = lohi(acc[i][b]);
                v += __shfl_xor_sync(0xffffffffu, v, 8);
                v += __shfl_xor_sync(0xffffffffu, v, 16);
                part[i][b] = v;
            }
        if (lane < 8) {
            #pragma unroll
            for (int i = 0; i < 6; ++i)
                #pragma unroll
                for (int b = 0; b < NB; ++b)
                    sred[warp][lane * 6 + i][b] = part[i][b];
        }
        __syncthreads();

        if (tid < 64) {
            float hr = bias_s[ul], hz = bias_s[16 + ul], hn = bias_s[32 + ul];
            #pragma unroll
            for (int w8 = 0; w8 < 8; ++w8) {
                hr += sred[w8][ul][bl];
                hz += sred[w8][16 + ul][bl];
                hn += sred[w8][32 + ul][bl];
            }
            float hold = hstage[bl][u0 + ul];
            float r = 1.f / (1.f + __expf(-(xpr + hr)));
            float z = 1.f / (1.f + __expf(-(xpz + hz)));
            float n = tanhf(xpn + r * hn);
            float hnew = (1.f - z) * n + z * hold;
            __stcg(&g_hgrp[grp][cur ^ 1][bl][u0 + ul], hnew);
            __stcs(&g_hs[((size_t)t * 16 + bglob) * RNN + u0 + ul], hnew);

            // gate warps only: order h stores, then publish this CTA's flag
            asm volatile("bar.sync 1, 64;" ::: "memory");
            if (tid == 0)
                asm volatile("st.release.gpu.global.u32 [%0], %1;"
                             :: "l"(myflag), "r"((unsigned)(t + 1)) : "memory");
        }

        // 32 parallel pollers: lane i of warp 0 watches CTA i's flag (own group)
        if (tid < GRP_CTAS) {
            unsigned* fp = &grpflags[tid * 8];
            unsigned v;
            do {
                asm volatile("ld.relaxed.gpu.global.u32 %0, [%1];"
                             : "=r"(v) : "l"(fp) : "memory");
            } while (v < (unsigned)(t + 1));
            asm volatile("fence.acquire.gpu;" ::: "memory");
        }
        __syncthreads();

        xpr = nxr; xpz = nxz; xpn = nxn;
        cur ^= 1;
    }
}

// ---------------- launcher ----------------
extern "C" void kernel_launch(void* const* d_in, const int* in_sizes, int n_in,
                              void* d_out, int out_size) {
    const int*   x     = (const int*)d_in[0];
    const float* mels  = (const float*)d_in[1];
    const float* upk0  = (const float*)d_in[2];
    const float* upk1  = (const float*)d_in[3];
    const float* upk2  = (const float*)d_in[4];
    const float* w_ih  = (const float*)d_in[5];
    const float* w_hh  = (const float*)d_in[6];
    const float* b_ih  = (const float*)d_in[7];
    const float* b_hh  = (const float*)d_in[8];
    const float* fc1_w = (const float*)d_in[9];
    const float* fc1_b = (const float*)d_in[10];
    const float* fc2_w = (const float*)d_in[11];
    const float* fc2_b = (const float*)d_in[12];
    float* out = (float*)d_out;

    float *melT, *xproj, *hs, *f1;
    cudaGetSymbolAddress((void**)&melT, g_melT);
    cudaGetSymbolAddress((void**)&xproj, g_xproj);
    cudaGetSymbolAddress((void**)&hs, g_hs);
    cudaGetSymbolAddress((void**)&f1, g_f1);

    // 1: init  2: fused upsample  3: xproj GEMM  4: GRU (ncu capture slot)
    // 5: fc1   6: fc2
    k_init<<<64, 256>>>();
    k_upsample_all<<<BATCH * FEAT, 256>>>(mels, upk0, upk1, upk2);

    k_gemm<<<dim3(M_ROWS / BM, G3 / BN), 256>>>(
        melT, FEAT, w_ih + NCLASS, D_IN, FEAT / BK, b_ih, xproj, 0, x, w_ih);

    k_gru<<<NGRP * GRP_CTAS, 256>>>(w_hh, b_hh);

    k_gemm<<<dim3(M_ROWS / BM, NCLASS / BN), 256>>>(
        hs, RNN, fc1_w, RNN, RNN / BK, fc1_b, f1, 1, nullptr, nullptr);

    k_gemm<<<dim3(M_ROWS / BM, NCLASS / BN), 256>>>(
        f1, RNN, fc2_w, NCLASS, NCLASS / BK, fc2_b, out, 2, nullptr, nullptr);

    (void)in_sizes; (void)n_in; (void)out_size;
}

// round 15
// speedup vs baseline: 1.4685x; 1.4685x over previous
#include <cuda_runtime.h>
#include <cuda_bf16.h>
#include <cstdint>

#define BATCH 16
#define T_MEL 16
#define FEAT 80
#define NCLASS 512
#define RNN 512
#define D_IN 592
#define G3 1536
#define T_OUT 3300
#define M_ROWS (T_OUT * BATCH)

#define NGRP 4          // independent batch groups
#define GRP_CTAS 32     // CTAs per group
#define NB 4            // batches per group
#define UNITS 16        // units per CTA  (32*16 = 512)

typedef unsigned long long ull;

// ---------------- device scratch (no allocation allowed) ----------------
__device__ float g_melT[(size_t)M_ROWS * FEAT];
__device__ float g_xproj[(size_t)M_ROWS * G3];
__device__ float g_hs[(size_t)M_ROWS * RNN];
__device__ float g_f1[(size_t)M_ROWS * RNN];
__device__ float g_hgrp[NGRP][2][NB][RNN];   // per-group ping-pong h
__device__ unsigned g_garr[NGRP * 64];       // group barrier counters, 256B apart

// ---------------- helpers ----------------
__device__ __forceinline__ ull pack2(float x, float y) {
    ull r; asm("mov.b64 %0,{%1,%2};" : "=l"(r) : "f"(x), "f"(y)); return r;
}
__device__ __forceinline__ void fma2(ull& d, ull a, ull b) {
    asm("fma.rn.f32x2 %0,%1,%2,%3;" : "=l"(d) : "l"(a), "l"(b), "l"(d));
}
__device__ __forceinline__ float lohi(ull a) {
    float x, y; asm("mov.b64 {%0,%1},%2;" : "=f"(x), "=f"(y) : "l"(a)); return x + y;
}
__device__ __forceinline__ void unpk(ull a, float& x, float& y) {
    asm("mov.b64 {%0,%1},%2;" : "=f"(x), "=f"(y) : "l"(a));
}

// ---------------- init ----------------
__global__ void k_init() {
    int i = blockIdx.x * blockDim.x + threadIdx.x;
    if (i < NGRP * 64) g_garr[i] = 0u;
    if (i < NGRP * 2 * NB * RNN) ((float*)g_hgrp)[i] = 0.f;
}

// ---------------- fused 3-stage upsample ----------------
__global__ void __launch_bounds__(256)
k_upsample_all(const float* __restrict__ mels,
               const float* __restrict__ k0,
               const float* __restrict__ k1,
               const float* __restrict__ k2) {
    __shared__ float s16[16];
    __shared__ float s80[80];
    __shared__ float s400[400];
    __shared__ float sk0[11], sk1[11], sk2[23];
    const int bf = blockIdx.x, b = bf / FEAT, f = bf % FEAT;
    const int tid = threadIdx.x;

    if (tid < 16) s16[tid] = mels[(size_t)bf * T_MEL + tid];
    if (tid < 11) { sk0[tid] = k0[tid]; sk1[tid] = k1[tid]; }
    if (tid < 23) sk2[tid] = k2[tid];
    __syncthreads();

    if (tid < 80) {
        float a = 0.f;
        #pragma unroll
        for (int j = 0; j < 11; ++j) {
            int u = tid + j - 5;
            if (u >= 0 && u < 80) a += sk0[j] * s16[u / 5];
        }
        s80[tid] = a;
    }
    __syncthreads();

    for (int t = tid; t < 400; t += 256) {
        float a = 0.f;
        #pragma unroll
        for (int j = 0; j < 11; ++j) {
            int u = t + j - 5;
            if (u >= 0 && u < 400) a += sk1[j] * s80[u / 5];
        }
        s400[t] = a;
    }
    __syncthreads();

    for (int t = tid; t < T_OUT; t += 256) {
        const int tp = t + 550;
        float a = 0.f;
        #pragma unroll
        for (int j = 0; j < 23; ++j) {
            int u = tp + j - 11;
            if (u >= 0 && u < 4400) a += sk2[j] * s400[u / 11];
        }
        g_melT[((size_t)t * BATCH + b) * FEAT + f] = a;
    }
}

// ---------------- fp32 GEMM (f32x2 inner): C[M,N] = A[M,K] @ B[N,K]^T -------
// mode 0: xproj (+b_ih + w_ih[g, x[b,t]]), mode 1: fc1 relu, mode 2: fc2 -> out
#define BM 64
#define BN 64
#define BK 16
#define SSTR 68

__global__ void __launch_bounds__(256)
k_gemm(const float* __restrict__ A, int lda,
       const float* __restrict__ Bw, int ldb, int KT,
       const float* __restrict__ bias, float* __restrict__ C,
       int mode, const int* __restrict__ xidx, const float* __restrict__ w_ih_full) {
    __shared__ float As[BK * SSTR];
    __shared__ float Bs[BK * SSTR];
    const int tid = threadIdx.x;
    const int m0 = blockIdx.x * BM, n0 = blockIdx.y * BN;
    const int ty = tid >> 4, tx = tid & 15;
    const int fr = tid >> 2, fc = (tid & 3) * 4;

    ull c2[4][2];   // [m][n-pair]: packs columns (2p, 2p+1)
    #pragma unroll
    for (int i = 0; i < 4; ++i) { c2[i][0] = 0ull; c2[i][1] = 0ull; }

    for (int kt = 0; kt < KT; ++kt) {
        const int k0 = kt * BK;
        float4 va = *reinterpret_cast<const float4*>(&A[(size_t)(m0 + fr) * lda + k0 + fc]);
        float4 vb = *reinterpret_cast<const float4*>(&Bw[(size_t)(n0 + fr) * ldb + k0 + fc]);
        As[(fc + 0) * SSTR + fr] = va.x; As[(fc + 1) * SSTR + fr] = va.y;
        As[(fc + 2) * SSTR + fr] = va.z; As[(fc + 3) * SSTR + fr] = va.w;
        Bs[(fc + 0) * SSTR + fr] = vb.x; Bs[(fc + 1) * SSTR + fr] = vb.y;
        Bs[(fc + 2) * SSTR + fr] = vb.z; Bs[(fc + 3) * SSTR + fr] = vb.w;
        __syncthreads();
        #pragma unroll
        for (int kk = 0; kk < BK; ++kk) {
            const ull* bp = reinterpret_cast<const ull*>(&Bs[kk * SSTR + tx * 4]);
            ull b01 = bp[0], b23 = bp[1];
            float4 a4 = *reinterpret_cast<const float4*>(&As[kk * SSTR + ty * 4]);
            ull a0 = pack2(a4.x, a4.x), a1 = pack2(a4.y, a4.y);
            ull a2 = pack2(a4.z, a4.z), a3 = pack2(a4.w, a4.w);
            fma2(c2[0][0], a0, b01); fma2(c2[0][1], a0, b23);
            fma2(c2[1][0], a1, b01); fma2(c2[1][1], a1, b23);
            fma2(c2[2][0], a2, b01); fma2(c2[2][1], a2, b23);
            fma2(c2[3][0], a3, b01); fma2(c2[3][1], a3, b23);
        }
        __syncthreads();
    }

    #pragma unroll
    for (int im = 0; im < 4; ++im) {
        float cc[4];
        unpk(c2[im][0], cc[0], cc[1]);
        unpk(c2[im][1], cc[2], cc[3]);
        const int r = m0 + ty * 4 + im;
        const int t = r >> 4, b = r & 15;
        int xv = 0;
        if (mode == 0) xv = xidx[b * T_OUT + t];
        #pragma unroll
        for (int in_ = 0; in_ < 4; ++in_) {
            const int g = n0 + tx * 4 + in_;
            float v = cc[in_] + bias[g];
            if (mode == 0) {
                v += w_ih_full[(size_t)g * D_IN + xv];
                C[(size_t)r * G3 + g] = v;
            } else if (mode == 1) {
                C[(size_t)r * RNN + g] = fmaxf(v, 0.f);
            } else {
                C[((size_t)b * T_OUT + t) * NCLASS + g] = v;
            }
        }
    }
}

// ---------------- persistent GRU: batch groups, weights in registers --------
// grid 128 = 4 groups x 32 CTAs. CTA: 16 units, 4 batches, 256 threads.
__global__ void __launch_bounds__(256, 1)
k_gru(const float* __restrict__ w_hh, const float* __restrict__ b_hh) {
    __shared__ float hstage[NB][RNN];          // this group's h (8 KB)
    __shared__ float sred[8][48][NB];          // per-warp partials
    __shared__ float bias_s[48];

    const int cta = blockIdx.x, grp = cta >> 5, c = cta & 31, u0 = c * UNITS;
    const int tid = threadIdx.x;
    const int rg = tid & 7, ks = tid >> 3, warp = tid >> 5, lane = tid & 31;
    const int ul = tid >> 2, bl = tid & 3;     // gate threads (tid<64)
    const int bglob = grp * NB + bl;

    // load weights into registers (static row/k mapping)
    ull w[6][8];
    #pragma unroll
    for (int i = 0; i < 6; ++i) {
        const int m = rg * 6 + i;               // 0..47
        const int gate = m >> 4, uloc = m & 15;
        const float* wp = w_hh + ((size_t)(gate * RNN + u0 + uloc)) * RNN + ks * 16;
        #pragma unroll
        for (int j = 0; j < 8; ++j)
            w[i][j] = *reinterpret_cast<const ull*>(wp + 2 * j);
    }
    if (tid < 48) bias_s[tid] = b_hh[(tid >> 4) * RNN + u0 + (tid & 15)];

    // x_proj preload for t = 0 (gate threads)
    float xpr = 0.f, xpz = 0.f, xpn = 0.f;
    if (tid < 64) {
        size_t ro = (size_t)bglob * G3 + u0 + ul;
        xpr = __ldg(&g_xproj[ro]);
        xpz = __ldg(&g_xproj[ro + 512]);
        xpn = __ldg(&g_xproj[ro + 1024]);
    }
    __syncthreads();

    unsigned* arrp = &g_garr[grp * 64];
    int cur = 0;
    for (int t = 0; t < T_OUT; ++t) {
        // stage this group's h (2048 floats) into smem cooperatively
        {
            const float* hsrc = &g_hgrp[grp][cur][0][0];
            float4 v0 = __ldcg(reinterpret_cast<const float4*>(hsrc + tid * 8));
            float4 v1 = __ldcg(reinterpret_cast<const float4*>(hsrc + tid * 8 + 4));
            *reinterpret_cast<float4*>(&hstage[0][0] + tid * 8) = v0;
            *reinterpret_cast<float4*>(&hstage[0][0] + tid * 8 + 4) = v1;
        }
        // prefetch next step's x_proj
        float nxr = 0.f, nxz = 0.f, nxn = 0.f;
        if (tid < 64 && t + 1 < T_OUT) {
            size_t ro = ((size_t)(t + 1) * 16 + bglob) * G3 + u0 + ul;
            nxr = __ldg(&g_xproj[ro]);
            nxz = __ldg(&g_xproj[ro + 512]);
            nxn = __ldg(&g_xproj[ro + 1024]);
        }
        __syncthreads();   // hstage ready

        // dot products: 6 rows x 16 k x 4 batches, weights in regs
        ull acc[6][NB];
        #pragma unroll
        for (int i = 0; i < 6; ++i)
            #pragma unroll
            for (int b = 0; b < NB; ++b) acc[i][b] = 0ull;

        #pragma unroll
        for (int b = 0; b < NB; ++b) {
            ull h2[8];
            #pragma unroll
            for (int j = 0; j < 4; ++j) {
                float4 v = *reinterpret_cast<const float4*>(&hstage[b][ks * 16 + 4 * j]);
                h2[2 * j]     = pack2(v.x, v.y);
                h2[2 * j + 1] = pack2(v.z, v.w);
            }
            #pragma unroll
            for (int i = 0; i < 6; ++i)
                #pragma unroll
                for (int j = 0; j < 8; ++j)
                    fma2(acc[i][b], w[i][j], h2[j]);
        }

        // reduce over k: lane bits 3,4 carry ks&3
        float part[6][NB];
        #pragma unroll
        for (int i = 0; i < 6; ++i)
            #pragma unroll
            for (int b = 0; b < NB; ++b) {
                float v = lohi(acc[i][b]);
                v += __shfl_xor_sync(0xffffffffu, v, 8);
                v += __shfl_xor_sync(0xffffffffu, v, 16);
                part[i][b] = v;
            }
        if (lane < 8) {
            #pragma unroll
            for (int i = 0; i < 6; ++i)
                #pragma unroll
                for (int b = 0; b < NB; ++b)
                    sred[warp][lane * 6 + i][b] = part[i][b];
        }
        __syncthreads();

        if (tid < 64) {
            float hr = bias_s[ul], hz = bias_s[16 + ul], hn = bias_s[32 + ul];
            #pragma unroll
            for (int w8 = 0; w8 < 8; ++w8) {
                hr += sred[w8][ul][bl];
                hz += sred[w8][16 + ul][bl];
                hn += sred[w8][32 + ul][bl];
            }
            float hold = hstage[bl][u0 + ul];
            float r = 1.f / (1.f + __expf(-(xpr + hr)));
            float z = 1.f / (1.f + __expf(-(xpz + hz)));
            float n = tanhf(xpn + r * hn);
            float hnew = (1.f - z) * n + z * hold;
            __stcg(&g_hgrp[grp][cur ^ 1][bl][u0 + ul], hnew);
            __stcs(&g_hs[((size_t)t * 16 + bglob) * RNN + u0 + ul], hnew);
        }
        __syncthreads();   // h stores issued before tid0's release

        // group-local barrier: 32 arrivals, release REDG + relaxed poll + acquire
        if (tid == 0) {
            asm volatile("red.release.gpu.global.add.u32 [%0], %1;"
                         :: "l"(arrp), "r"(1u) : "memory");
            const unsigned tgt = (unsigned)(t + 1) * GRP_CTAS;
            unsigned v;
            do {
                asm volatile("ld.relaxed.gpu.global.u32 %0, [%1];"
                             : "=r"(v) : "l"(arrp) : "memory");
            } while (v < tgt);
            asm volatile("fence.acquire.gpu;" ::: "memory");
        }
        __syncthreads();

        xpr = nxr; xpz = nxz; xpn = nxn;
        cur ^= 1;
    }
}

// ---------------- launcher ----------------
extern "C" void kernel_launch(void* const* d_in, const int* in_sizes, int n_in,
                              void* d_out, int out_size) {
    const int*   x     = (const int*)d_in[0];
    const float* mels  = (const float*)d_in[1];
    const float* upk0  = (const float*)d_in[2];
    const float* upk1  = (const float*)d_in[3];
    const float* upk2  = (const float*)d_in[4];
    const float* w_ih  = (const float*)d_in[5];
    const float* w_hh  = (const float*)d_in[6];
    const float* b_ih  = (const float*)d_in[7];
    const float* b_hh  = (const float*)d_in[8];
    const float* fc1_w = (const float*)d_in[9];
    const float* fc1_b = (const float*)d_in[10];
    const float* fc2_w = (const float*)d_in[11];
    const float* fc2_b = (const float*)d_in[12];
    float* out = (float*)d_out;

    float *melT, *xproj, *hs, *f1;
    cudaGetSymbolAddress((void**)&melT, g_melT);
    cudaGetSymbolAddress((void**)&xproj, g_xproj);
    cudaGetSymbolAddress((void**)&hs, g_hs);
    cudaGetSymbolAddress((void**)&f1, g_f1);

    // 1: init  2: fused upsample  3: xproj GEMM  4: GRU (ncu capture slot)
    // 5: fc1   6: fc2
    k_init<<<64, 256>>>();
    k_upsample_all<<<BATCH * FEAT, 256>>>(mels, upk0, upk1, upk2);

    k_gemm<<<dim3(M_ROWS / BM, G3 / BN), 256>>>(
        melT, FEAT, w_ih + NCLASS, D_IN, FEAT / BK, b_ih, xproj, 0, x, w_ih);

    k_gru<<<NGRP * GRP_CTAS, 256>>>(w_hh, b_hh);

    k_gemm<<<dim3(M_ROWS / BM, NCLASS / BN), 256>>>(
        hs, RNN, fc1_w, RNN, RNN / BK, fc1_b, f1, 1, nullptr, nullptr);

    k_gemm<<<dim3(M_ROWS / BM, NCLASS / BN), 256>>>(
        f1, RNN, fc2_w, NCLASS, NCLASS / BK, fc2_b, out, 2, nullptr, nullptr);

    (void)in_sizes; (void)n_in; (void)out_size;
}